// round 14
// baseline (speedup 1.0000x reference)
#include <cuda_runtime.h>
#include <cuda_fp16.h>
#include <math.h>
#include <stdint.h>

#define D    256
#define NPN  128
#define GN   1024

__device__ __forceinline__ float silu_f(float v){ return __fdividef(v, 1.f + __expf(-v)); }
__device__ __forceinline__ float sigm_f(float v){ return __fdividef(1.f, 1.f + __expf(-v)); }

__device__ float g_PiE[GN*D], g_PjE[GN*D], g_PiX[GN*D], g_PjX[GN*D], g_msg[GN*D];
__device__ __align__(16) __half g_W1h[2][256*64];      // [ch][n*64+k]
__device__ float g_w64[2][256];                         // sq-row weights (k=64)
__device__ __align__(16) __half g_W2h[2][256*256];     // [ch][n*256+k]

// m16n8k16 fp16 mma, fp32 accum
__device__ __forceinline__ void mma16(float c[4], uint32_t a0, uint32_t a1, uint32_t a2, uint32_t a3,
                                      uint32_t b0, uint32_t b1){
    asm volatile("mma.sync.aligned.m16n8k16.row.col.f32.f16.f16.f32 "
        "{%0,%1,%2,%3},{%4,%5,%6,%7},{%8,%9},{%0,%1,%2,%3};"
        : "+f"(c[0]),"+f"(c[1]),"+f"(c[2]),"+f"(c[3])
        : "r"(a0),"r"(a1),"r"(a2),"r"(a3),"r"(b0),"r"(b1));
}

// ---------------- edge SMEM layout (floats) ----------------
#define FHO   0          // f tile half [128][72]  = 4608 floats
#define E1O   4608       // E1 half [128][264] = 16896 floats ; also m-stash
#define MB    21504
#define MPI   (MB+0)
#define MW64  (MB+256)
#define MB2   (MB+512)
#define MWV   (MB+768)
#define MDX   (MB+1024)
#define MDY   (MB+1152)
#define MDZ   (MB+1280)
#define MRN   (MB+1408)
#define MAD   (MB+1536)
#define MSQ   (MB+1664)
#define MWG   (MB+1792)
#define MRS   (MB+1920)
#define MCR   (MB+2048)
#define MNN   (MB+2052)
#define SM_FLOATS (MB+2056)
#define SMEM_BYTES (SM_FLOATS*4)   // 94240 B

// node kernel dynamic smem (floats): 4 nodes/CTA
#define ND_CAT  0              // 4*512
#define ND_WS   2048           // 32*256
#define ND_H1   10240          // 4*256
#define ND_FLOATS 11264
#define ND_BYTES (ND_FLOATS*4) // 45056 B

// =====================================================================
// prep: fp16 transposed weight operands + w64 rows
// =====================================================================
__global__ void prep_kernel(const float* __restrict__ We1, const float* __restrict__ Wx1,
                            const float* __restrict__ We2, const float* __restrict__ Wx2)
{
    int i = blockIdx.x*blockDim.x + threadIdx.x;
    if (i < 2*256*64){
        int ch = i/16384, j = i%16384, n = j>>6, k = j&63;
        const float* W = ch ? Wx1 : We1;
        g_W1h[ch][j] = __float2half(W[(512+k)*D + n]);
    }
    if (i < 512){
        int ch = i>>8, n = i&255;
        g_w64[ch][n] = (ch ? Wx1 : We1)[576*D + n];
    }
    if (i < 2*256*256){
        int ch = i/65536, j = i%65536, n = j>>8, k = j&255;
        const float* W = ch ? Wx2 : We2;
        g_W2h[ch][j] = __float2half(W[k*D + n]);
    }
}

// =====================================================================
// proj: 4 nodes/CTA, grid 256
// =====================================================================
__global__ void __launch_bounds__(256)
proj_kernel(const float* __restrict__ inv,
            const float* __restrict__ We1, const float* __restrict__ be1,
            const float* __restrict__ Wx1, const float* __restrict__ bx1)
{
    __shared__ float invs[4*256];
    __shared__ float ws[32*256];
    const int g0 = blockIdx.x*4, c = threadIdx.x, tid = threadIdx.x;
    #pragma unroll
    for (int r=0;r<4;++r) invs[r*256+c] = inv[(size_t)(g0+r)*D + c];

    #pragma unroll 1
    for (int m=0; m<4; ++m){
        const float* W = ((m<2) ? We1 : Wx1) + (size_t)(m&1)*D*D;
        float acc[4];
        float b = (m==0) ? be1[c] : ((m==2) ? bx1[c] : 0.f);
        #pragma unroll
        for (int r=0;r<4;++r) acc[r]=b;
        #pragma unroll 1
        for (int kc=0; kc<8; ++kc){
            __syncthreads();
            {
                int row = (tid>>6), c4 = tid&63;
                #pragma unroll
                for (int it=0; it<8; ++it)
                    ((float4*)ws)[(row+it*4)*64 + c4] =
                        ((const float4*)(W + (size_t)(kc*32 + row + it*4)*D))[c4];
            }
            __syncthreads();
            #pragma unroll 8
            for (int k=0;k<32;++k){
                float w = ws[k*256+c];
                int kk = kc*32+k;
                #pragma unroll
                for (int r=0;r<4;++r) acc[r] += invs[r*256+kk]*w;
            }
        }
        float* dst = (m==0)?g_PiE : (m==1)?g_PjE : (m==2)?g_PiX : g_PjX;
        #pragma unroll
        for (int r=0;r<4;++r) dst[(size_t)(g0+r)*D + c] = acc[r];
        __syncthreads();
    }
}

// =====================================================================
// edge kernel: fp16 mma, B-fragments from L2, minimal barriers
// =====================================================================
__global__ void __launch_bounds__(256,1)
edge_kernel(const float* __restrict__ coords, const float* __restrict__ adj,
            const float* __restrict__ amask,  const float* __restrict__ ef,
            const float* __restrict__ be2,    const float* __restrict__ Watt,
            const float* __restrict__ batt,   const float* __restrict__ bx2,
            const float* __restrict__ Wx3,    const float* __restrict__ bx3,
            float* __restrict__ outc)
{
    extern __shared__ float sm[];
    __half* FH  = (__half*)(sm + FHO);
    __half* E1H = (__half*)(sm + E1O);

    const int gi   = blockIdx.x;
    const int bi   = gi >> 7;
    const int tid  = threadIdx.x;
    const int warp = tid >> 5;
    const int lane = tid & 31;
    const int wm   = warp >> 1;       // 0..3  (M groups of 32)
    const int wn   = warp & 1;        // 0..1  (N halves of 128)
    const int qr   = lane >> 2;       // 0..7
    const int qc   = lane & 3;        // 0..3

    if (tid < 4) sm[MCR + tid] = 0.f;
    if (tid == 0) sm[MNN] = 1.f;
    const float cx = coords[gi*3+0], cy = coords[gi*3+1], cz = coords[gi*3+2];
    if (tid < NPN){
        const float* cj = coords + (size_t)(bi*NPN + tid)*3;
        float dx = cx-cj[0], dy = cy-cj[1], dz = cz-cj[2];
        float sq = dx*dx + dy*dy + dz*dz;
        sm[MDX+tid]=dx; sm[MDY+tid]=dy; sm[MDZ+tid]=dz;
        sm[MSQ+tid]=sq;
        sm[MRN+tid]=__fdividef(1.f, sqrtf(sq + 1e-5f) + 1.f);
        sm[MAD+tid]=adj[(size_t)gi*NPN + tid];
    }
    __syncthreads();
    if (tid < NPN) atomicAdd(&sm[MNN], amask[bi*NPN + tid]);
    const float battv = batt[0], bx3v = bx3[0];

    // build f tile half [128][72] once (k<64 from ef)
    #pragma unroll
    for (int it=0; it<32; ++it){
        int idx = tid + it*256; int j = idx>>6; int k = idx&63;
        FH[j*72 + k] = __float2half(ef[((size_t)gi*NPN + j)*64 + k]);
    }

    #pragma unroll 1
    for (int ch = 0; ch < 2; ++ch){
        sm[MPI+tid]  = ch ? g_PiX[gi*D+tid] : g_PiE[gi*D+tid];
        sm[MW64+tid] = g_w64[ch][tid];
        sm[MB2+tid]  = ch ? bx2[tid] : be2[tid];
        sm[MWV+tid]  = ch ? Wx3[tid] : Watt[tid];
        if (tid < NPN) sm[MRS+tid] = 0.f;
        __syncthreads();

        float cc[2][16][4];
        #pragma unroll
        for (int mt=0;mt<2;++mt)
            #pragma unroll
            for (int nt=0;nt<16;++nt)
                #pragma unroll
                for (int q=0;q<4;++q) cc[mt][nt][q]=0.f;

        // ---- chain-1 mma: [128 x 64] @ [64 x 256], B from L2 ----
        {
            const __half* W1g = g_W1h[ch];
            #pragma unroll
            for (int ks=0; ks<4; ++ks){
                int k0 = ks*16;
                uint32_t a[2][4];
                #pragma unroll
                for (int mt=0;mt<2;++mt){
                    int rb = wm*32 + mt*16 + qr;
                    a[mt][0] = *(const uint32_t*)&FH[rb*72     + k0 + 2*qc];
                    a[mt][1] = *(const uint32_t*)&FH[(rb+8)*72 + k0 + 2*qc];
                    a[mt][2] = *(const uint32_t*)&FH[rb*72     + k0 + 2*qc + 8];
                    a[mt][3] = *(const uint32_t*)&FH[(rb+8)*72 + k0 + 2*qc + 8];
                }
                #pragma unroll
                for (int nt=0;nt<16;++nt){
                    int nl = wn*128 + nt*8 + qr;
                    uint32_t b0 = *(const uint32_t*)&W1g[nl*64 + k0 + 2*qc];
                    uint32_t b1 = *(const uint32_t*)&W1g[nl*64 + k0 + 2*qc + 8];
                    mma16(cc[0][nt], a[0][0],a[0][1],a[0][2],a[0][3], b0, b1);
                    mma16(cc[1][nt], a[1][0],a[1][1],a[1][2],a[1][3], b0, b1);
                }
            }
        }
        // ---- epilogue 1: + sq*w64 + Pi + Pj, silu -> E1 (half) ----
        {
            const float* PjG = (ch ? g_PjX : g_PjE) + (size_t)(bi*NPN)*D;
            #pragma unroll
            for (int mt=0;mt<2;++mt){
                int row = wm*32 + mt*16 + qr;
                float sq0 = sm[MSQ+row], sq8 = sm[MSQ+row+8];
                #pragma unroll
                for (int nt=0;nt<16;++nt){
                    int colg = wn*128 + nt*8 + 2*qc;
                    float2 p0 = *(const float2*)(PjG + (size_t)row*D + colg);
                    float2 p8 = *(const float2*)(PjG + (size_t)(row+8)*D + colg);
                    float w0 = sm[MW64+colg], w1 = sm[MW64+colg+1];
                    float pi0 = sm[MPI+colg], pi1 = sm[MPI+colg+1];
                    float v0 = silu_f(cc[mt][nt][0] + sq0*w0 + pi0 + p0.x);
                    float v1 = silu_f(cc[mt][nt][1] + sq0*w1 + pi1 + p0.y);
                    float v2 = silu_f(cc[mt][nt][2] + sq8*w0 + pi0 + p8.x);
                    float v3 = silu_f(cc[mt][nt][3] + sq8*w1 + pi1 + p8.y);
                    *(half2*)&E1H[row*264 + colg]     = __floats2half2_rn(v0, v1);
                    *(half2*)&E1H[(row+8)*264 + colg] = __floats2half2_rn(v2, v3);
                }
            }
        }
        __syncthreads();   // E1 complete (all warps)

        // ---- chain-2 mma: [128 x 256] @ [256 x 256], B from L2 ----
        #pragma unroll
        for (int mt=0;mt<2;++mt)
            #pragma unroll
            for (int nt=0;nt<16;++nt)
                #pragma unroll
                for (int q=0;q<4;++q) cc[mt][nt][q]=0.f;

        {
            const __half* W2g = g_W2h[ch];
            #pragma unroll 2
            for (int kt = 0; kt < 16; ++kt){
                int kg = kt*16;
                uint32_t a[2][4];
                #pragma unroll
                for (int mt=0;mt<2;++mt){
                    int rb = wm*32 + mt*16 + qr;
                    a[mt][0] = *(const uint32_t*)&E1H[rb*264     + kg + 2*qc];
                    a[mt][1] = *(const uint32_t*)&E1H[(rb+8)*264 + kg + 2*qc];
                    a[mt][2] = *(const uint32_t*)&E1H[rb*264     + kg + 2*qc + 8];
                    a[mt][3] = *(const uint32_t*)&E1H[(rb+8)*264 + kg + 2*qc + 8];
                }
                #pragma unroll
                for (int nt=0;nt<16;++nt){
                    int nl = wn*128 + nt*8 + qr;
                    uint32_t b0 = *(const uint32_t*)&W2g[nl*256 + kg + 2*qc];
                    uint32_t b1 = *(const uint32_t*)&W2g[nl*256 + kg + 2*qc + 8];
                    mma16(cc[0][nt], a[0][0],a[0][1],a[0][2],a[0][3], b0, b1);
                    mma16(cc[1][nt], a[1][0],a[1][1],a[1][2],a[1][3], b0, b1);
                }
            }
        }
        __syncthreads();   // all E1 reads done; E1 region free for m stash

        // ---- epilogue 2: rowsum + (ch0) half m-stash ----
        #pragma unroll
        for (int mt=0;mt<2;++mt){
            int row = wm*32 + mt*16 + qr;
            float pr0 = 0.f, pr8 = 0.f;
            #pragma unroll
            for (int nt=0;nt<16;++nt){
                int colg = wn*128 + nt*8 + 2*qc;
                float b0 = sm[MB2+colg], b1c = sm[MB2+colg+1];
                float w0 = sm[MWV+colg], w1 = sm[MWV+colg+1];
                float s0 = silu_f(cc[mt][nt][0]+b0);
                float s1 = silu_f(cc[mt][nt][1]+b1c);
                float s2 = silu_f(cc[mt][nt][2]+b0);
                float s3 = silu_f(cc[mt][nt][3]+b1c);
                pr0 += s0*w0 + s1*w1;
                pr8 += s2*w0 + s3*w1;
                if (ch == 0){
                    *(half2*)&E1H[row*264 + colg]     = __floats2half2_rn(s0, s1);
                    *(half2*)&E1H[(row+8)*264 + colg] = __floats2half2_rn(s2, s3);
                }
            }
            pr0 += __shfl_xor_sync(0xffffffffu, pr0, 1);
            pr0 += __shfl_xor_sync(0xffffffffu, pr0, 2);
            pr8 += __shfl_xor_sync(0xffffffffu, pr8, 1);
            pr8 += __shfl_xor_sync(0xffffffffu, pr8, 2);
            if (qc == 0){
                atomicAdd(&sm[MRS + row],     pr0);
                atomicAdd(&sm[MRS + row + 8], pr8);
            }
        }
        __syncthreads();

        if (tid < NPN){
            if (ch == 0)
                sm[MWG+tid] = sigm_f(sm[MRS+tid] + battv) * sm[MAD+tid];
            else
                sm[MWG+tid] = (sm[MRS+tid] + bx3v) * sm[MRN+tid] * sm[MAD+tid];
        }
        __syncthreads();

        if (ch == 0){
            float s = 0.f;
            #pragma unroll 8
            for (int j = 0; j < NPN; ++j)
                s += __half2float(E1H[j*264 + tid]) * sm[MWG+j];
            g_msg[gi*D + tid] = s;
        } else {
            if (warp < 4){
                int j = warp*32 + lane;
                float w = sm[MWG+j];
                float a0 = sm[MDX+j]*w, a1 = sm[MDY+j]*w, a2 = sm[MDZ+j]*w;
                #pragma unroll
                for (int off=16; off>=1; off>>=1){
                    a0 += __shfl_down_sync(0xffffffffu, a0, off);
                    a1 += __shfl_down_sync(0xffffffffu, a1, off);
                    a2 += __shfl_down_sync(0xffffffffu, a2, off);
                }
                if (lane == 0){
                    atomicAdd(&sm[MCR+0], a0);
                    atomicAdd(&sm[MCR+1], a1);
                    atomicAdd(&sm[MCR+2], a2);
                }
            }
        }
        __syncthreads();
    }

    if (tid < 3){
        float upd = sm[MCR+tid] / sm[MNN];
        outc[gi*3 + tid] = (coords[gi*3 + tid] + upd) * amask[gi];
    }
}

// =====================================================================
// node MLP: 4 nodes/CTA, grid 256, dynamic smem
// =====================================================================
__global__ void __launch_bounds__(256)
node_kernel(const float* __restrict__ inv, const float* __restrict__ amask,
            const float* __restrict__ Wh1, const float* __restrict__ bh1,
            const float* __restrict__ Wh2, const float* __restrict__ bh2,
            float* __restrict__ outf)
{
    extern __shared__ float nsm[];
    float* cat = nsm + ND_CAT;    // [4][512]
    float* ws  = nsm + ND_WS;     // [32][256]
    float* h1  = nsm + ND_H1;     // [4][256]
    const int g0 = blockIdx.x*4, c = threadIdx.x, tid = threadIdx.x;
    #pragma unroll
    for (int r=0;r<4;++r){
        cat[r*512 + c]       = inv[(size_t)(g0+r)*D + c];
        cat[r*512 + 256 + c] = g_msg[(size_t)(g0+r)*D + c];
    }

    float acc[4];
    float b1 = bh1[c];
    #pragma unroll
    for (int r=0;r<4;++r) acc[r]=b1;
    #pragma unroll 1
    for (int kc=0; kc<16; ++kc){
        __syncthreads();
        {
            int row = tid>>6, c4 = tid&63;
            #pragma unroll
            for (int it=0; it<8; ++it)
                ((float4*)ws)[(row+it*4)*64 + c4] =
                    ((const float4*)(Wh1 + (size_t)(kc*32 + row + it*4)*D))[c4];
        }
        __syncthreads();
        #pragma unroll 8
        for (int k=0;k<32;++k){
            float w = ws[k*256+c];
            int kk = kc*32+k;
            #pragma unroll
            for (int r=0;r<4;++r) acc[r] += cat[r*512+kk]*w;
        }
    }
    #pragma unroll
    for (int r=0;r<4;++r) h1[r*256+c] = silu_f(acc[r]);
    __syncthreads();

    float b2 = bh2[c];
    #pragma unroll
    for (int r=0;r<4;++r) acc[r]=b2;
    #pragma unroll 1
    for (int kc=0; kc<8; ++kc){
        __syncthreads();
        {
            int row = tid>>6, c4 = tid&63;
            #pragma unroll
            for (int it=0; it<8; ++it)
                ((float4*)ws)[(row+it*4)*64 + c4] =
                    ((const float4*)(Wh2 + (size_t)(kc*32 + row + it*4)*D))[c4];
        }
        __syncthreads();
        #pragma unroll 8
        for (int k=0;k<32;++k){
            float w = ws[k*256+c];
            int kk = kc*32+k;
            #pragma unroll
            for (int r=0;r<4;++r) acc[r] += h1[r*256+kk]*w;
        }
    }
    #pragma unroll
    for (int r=0;r<4;++r) outf[(size_t)(g0+r)*D + c] = acc[r]*amask[g0+r];
}

// =====================================================================
extern "C" void kernel_launch(void* const* d_in, const int* in_sizes, int n_in,
                              void* d_out, int out_size)
{
    const float* coords = (const float*)d_in[0];
    const float* inv    = (const float*)d_in[1];
    const float* adj    = (const float*)d_in[2];
    const float* amask  = (const float*)d_in[3];
    const float* ef     = (const float*)d_in[4];
    const float* We1    = (const float*)d_in[5];
    const float* be1    = (const float*)d_in[6];
    const float* We2    = (const float*)d_in[7];
    const float* be2    = (const float*)d_in[8];
    const float* Watt   = (const float*)d_in[9];
    const float* batt   = (const float*)d_in[10];
    const float* Wh1    = (const float*)d_in[11];
    const float* bh1    = (const float*)d_in[12];
    const float* Wh2    = (const float*)d_in[13];
    const float* bh2    = (const float*)d_in[14];
    const float* Wx1    = (const float*)d_in[15];
    const float* bx1    = (const float*)d_in[16];
    const float* Wx2    = (const float*)d_in[17];
    const float* bx2    = (const float*)d_in[18];
    const float* Wx3    = (const float*)d_in[19];
    const float* bx3    = (const float*)d_in[20];

    float* out  = (float*)d_out;
    float* outc = out;            // [8,128,3]
    float* outf = out + GN*3;     // [8,128,256]

    cudaFuncSetAttribute(edge_kernel, cudaFuncAttributeMaxDynamicSharedMemorySize, SMEM_BYTES);
    cudaFuncSetAttribute(node_kernel, cudaFuncAttributeMaxDynamicSharedMemorySize, ND_BYTES);

    prep_kernel<<<512, 256>>>(We1, Wx1, We2, Wx2);
    proj_kernel<<<GN/4, 256>>>(inv, We1, be1, Wx1, bx1);
    edge_kernel<<<GN, 256, SMEM_BYTES>>>(coords, adj, amask, ef,
                                         be2, Watt, batt, bx2, Wx3, bx3, outc);
    node_kernel<<<GN/4, 256, ND_BYTES>>>(inv, amask, Wh1, bh1, Wh2, bh2, outf);
}

// round 15
// speedup vs baseline: 1.5529x; 1.5529x over previous
#include <cuda_runtime.h>
#include <cuda_fp16.h>
#include <math.h>
#include <stdint.h>

#define D    256
#define NPN  128
#define GN   1024

__device__ __forceinline__ float silu_f(float v){ return __fdividef(v, 1.f + __expf(-v)); }
__device__ __forceinline__ float sigm_f(float v){ return __fdividef(1.f, 1.f + __expf(-v)); }

__device__ float g_PiE[GN*D], g_PjE[GN*D], g_PiX[GN*D], g_PjX[GN*D], g_msg[GN*D];
__device__ __align__(16) __half g_W1h[2][256*72];      // [ch][n*72+k], k<64 data
__device__ float g_w64[2][256];                         // sq-row weights (k=64)
__device__ __align__(16) __half g_W2h[2][256*264];     // [ch][n*264+k], k<256 data (264 = padded stride)

// m16n8k16 fp16 mma, fp32 accum
__device__ __forceinline__ void mma16(float c[4], uint32_t a0, uint32_t a1, uint32_t a2, uint32_t a3,
                                      uint32_t b0, uint32_t b1){
    asm volatile("mma.sync.aligned.m16n8k16.row.col.f32.f16.f16.f32 "
        "{%0,%1,%2,%3},{%4,%5,%6,%7},{%8,%9},{%0,%1,%2,%3};"
        : "+f"(c[0]),"+f"(c[1]),"+f"(c[2]),"+f"(c[3])
        : "r"(a0),"r"(a1),"r"(a2),"r"(a3),"r"(b0),"r"(b1));
}

// ---------------- edge SMEM layout (floats) ----------------
#define FHO   0          // f tile half [128][72]  = 4608 floats
#define WSO   4608       // weight buf: W1 half [256][72] (9216 fl) OR W2 half [256][264] (33792 fl)
#define E1O   38400      // E1 half [128][264] = 16896 floats ; also m-stash
#define MB    55296
#define MPI   (MB+0)
#define MW64  (MB+256)
#define MB2   (MB+512)
#define MWV   (MB+768)
#define MDX   (MB+1024)
#define MDY   (MB+1152)
#define MDZ   (MB+1280)
#define MRN   (MB+1408)
#define MAD   (MB+1536)
#define MSQ   (MB+1664)
#define MWG   (MB+1792)
#define MRS   (MB+1920)
#define MCR   (MB+2048)
#define MNN   (MB+2052)
#define SM_FLOATS (MB+2056)
#define SMEM_BYTES (SM_FLOATS*4)   // 229408 B  (< 232448 cap)

// node kernel dynamic smem (floats): 4 nodes/CTA
#define ND_CAT  0              // 4*512
#define ND_WS   2048           // 32*256
#define ND_H1   10240          // 4*256
#define ND_FLOATS 11264
#define ND_BYTES (ND_FLOATS*4) // 45056 B

// =====================================================================
// prep: fp16 transposed weight operands + w64 rows
// =====================================================================
__global__ void prep_kernel(const float* __restrict__ We1, const float* __restrict__ Wx1,
                            const float* __restrict__ We2, const float* __restrict__ Wx2)
{
    int i = blockIdx.x*blockDim.x + threadIdx.x;
    if (i < 2*256*72){
        int ch = i/18432, j = i%18432, n = j/72, k = j%72;
        const float* W = ch ? Wx1 : We1;
        g_W1h[ch][j] = __float2half((k<64) ? W[(512+k)*D + n] : 0.f);
    }
    if (i < 512){
        int ch = i>>8, n = i&255;
        g_w64[ch][n] = (ch ? Wx1 : We1)[576*D + n];
    }
    if (i < 2*256*256){
        int ch = i/65536, j = i%65536, n = j>>8, k = j&255;
        const float* W = ch ? Wx2 : We2;
        g_W2h[ch][n*264 + k] = __float2half(W[k*D + n]);
    }
}

// =====================================================================
// proj: 4 nodes/CTA, grid 256
// =====================================================================
__global__ void __launch_bounds__(256)
proj_kernel(const float* __restrict__ inv,
            const float* __restrict__ We1, const float* __restrict__ be1,
            const float* __restrict__ Wx1, const float* __restrict__ bx1)
{
    __shared__ float invs[4*256];
    __shared__ float ws[32*256];
    const int g0 = blockIdx.x*4, c = threadIdx.x, tid = threadIdx.x;
    #pragma unroll
    for (int r=0;r<4;++r) invs[r*256+c] = inv[(size_t)(g0+r)*D + c];

    #pragma unroll 1
    for (int m=0; m<4; ++m){
        const float* W = ((m<2) ? We1 : Wx1) + (size_t)(m&1)*D*D;
        float acc[4];
        float b = (m==0) ? be1[c] : ((m==2) ? bx1[c] : 0.f);
        #pragma unroll
        for (int r=0;r<4;++r) acc[r]=b;
        #pragma unroll 1
        for (int kc=0; kc<8; ++kc){
            __syncthreads();
            {
                int row = (tid>>6), c4 = tid&63;
                #pragma unroll
                for (int it=0; it<8; ++it)
                    ((float4*)ws)[(row+it*4)*64 + c4] =
                        ((const float4*)(W + (size_t)(kc*32 + row + it*4)*D))[c4];
            }
            __syncthreads();
            #pragma unroll 8
            for (int k=0;k<32;++k){
                float w = ws[k*256+c];
                int kk = kc*32+k;
                #pragma unroll
                for (int r=0;r<4;++r) acc[r] += invs[r*256+kk]*w;
            }
        }
        float* dst = (m==0)?g_PiE : (m==1)?g_PjE : (m==2)?g_PiX : g_PjX;
        #pragma unroll
        for (int r=0;r<4;++r) dst[(size_t)(g0+r)*D + c] = acc[r];
        __syncthreads();
    }
}

// =====================================================================
// edge kernel: fp16 mma, W2 fully SMEM-resident per chain
// =====================================================================
__global__ void __launch_bounds__(256,1)
edge_kernel(const float* __restrict__ coords, const float* __restrict__ adj,
            const float* __restrict__ amask,  const float* __restrict__ ef,
            const float* __restrict__ be2,    const float* __restrict__ Watt,
            const float* __restrict__ batt,   const float* __restrict__ bx2,
            const float* __restrict__ Wx3,    const float* __restrict__ bx3,
            float* __restrict__ outc)
{
    extern __shared__ float sm[];
    __half* FH  = (__half*)(sm + FHO);
    __half* WSH = (__half*)(sm + WSO);
    __half* E1H = (__half*)(sm + E1O);

    const int gi   = blockIdx.x;
    const int bi   = gi >> 7;
    const int tid  = threadIdx.x;
    const int warp = tid >> 5;
    const int lane = tid & 31;
    const int wm   = warp >> 1;       // 0..3  (M groups of 32)
    const int wn   = warp & 1;        // 0..1  (N halves of 128)
    const int qr   = lane >> 2;       // 0..7
    const int qc   = lane & 3;        // 0..3

    if (tid < 4) sm[MCR + tid] = 0.f;
    if (tid == 0) sm[MNN] = 1.f;
    const float cx = coords[gi*3+0], cy = coords[gi*3+1], cz = coords[gi*3+2];
    if (tid < NPN){
        const float* cj = coords + (size_t)(bi*NPN + tid)*3;
        float dx = cx-cj[0], dy = cy-cj[1], dz = cz-cj[2];
        float sq = dx*dx + dy*dy + dz*dz;
        sm[MDX+tid]=dx; sm[MDY+tid]=dy; sm[MDZ+tid]=dz;
        sm[MSQ+tid]=sq;
        sm[MRN+tid]=__fdividef(1.f, sqrtf(sq + 1e-5f) + 1.f);
        sm[MAD+tid]=adj[(size_t)gi*NPN + tid];
    }
    __syncthreads();
    if (tid < NPN) atomicAdd(&sm[MNN], amask[bi*NPN + tid]);
    const float battv = batt[0], bx3v = bx3[0];

    // build f tile half [128][72] once (k<64 from ef)
    #pragma unroll
    for (int it=0; it<32; ++it){
        int idx = tid + it*256; int j = idx>>6; int k = idx&63;
        FH[j*72 + k] = __float2half(ef[((size_t)gi*NPN + j)*64 + k]);
    }

    #pragma unroll 1
    for (int ch = 0; ch < 2; ++ch){
        sm[MPI+tid]  = ch ? g_PiX[gi*D+tid] : g_PiE[gi*D+tid];
        sm[MW64+tid] = g_w64[ch][tid];
        sm[MB2+tid]  = ch ? bx2[tid] : be2[tid];
        sm[MWV+tid]  = ch ? Wx3[tid] : Watt[tid];
        if (tid < NPN) sm[MRS+tid] = 0.f;
        // copy W1h (9216 floats = 2304 float4)
        {
            const float4* s4 = (const float4*)g_W1h[ch];
            float4* d4 = (float4*)(sm + WSO);
            #pragma unroll
            for (int it=0; it<9; ++it) d4[tid + it*256] = s4[tid + it*256];
        }
        __syncthreads();

        float cc[2][16][4];
        #pragma unroll
        for (int mt=0;mt<2;++mt)
            #pragma unroll
            for (int nt=0;nt<16;++nt)
                #pragma unroll
                for (int q=0;q<4;++q) cc[mt][nt][q]=0.f;

        // ---- chain-1 mma: [128 x 64] @ [64 x 256] ----
        #pragma unroll
        for (int ks=0; ks<4; ++ks){
            int k0 = ks*16;
            uint32_t a[2][4];
            #pragma unroll
            for (int mt=0;mt<2;++mt){
                int rb = wm*32 + mt*16 + qr;
                a[mt][0] = *(const uint32_t*)&FH[rb*72     + k0 + 2*qc];
                a[mt][1] = *(const uint32_t*)&FH[(rb+8)*72 + k0 + 2*qc];
                a[mt][2] = *(const uint32_t*)&FH[rb*72     + k0 + 2*qc + 8];
                a[mt][3] = *(const uint32_t*)&FH[(rb+8)*72 + k0 + 2*qc + 8];
            }
            #pragma unroll
            for (int nt=0;nt<16;++nt){
                int nl = wn*128 + nt*8 + qr;
                uint32_t b0 = *(const uint32_t*)&WSH[nl*72 + k0 + 2*qc];
                uint32_t b1 = *(const uint32_t*)&WSH[nl*72 + k0 + 2*qc + 8];
                mma16(cc[0][nt], a[0][0],a[0][1],a[0][2],a[0][3], b0, b1);
                mma16(cc[1][nt], a[1][0],a[1][1],a[1][2],a[1][3], b0, b1);
            }
        }
        // ---- epilogue 1: + sq*w64 + Pi + Pj, silu -> E1 (half) ----
        {
            const float* PjG = (ch ? g_PjX : g_PjE) + (size_t)(bi*NPN)*D;
            #pragma unroll
            for (int mt=0;mt<2;++mt){
                int row = wm*32 + mt*16 + qr;
                float sq0 = sm[MSQ+row], sq8 = sm[MSQ+row+8];
                #pragma unroll
                for (int nt=0;nt<16;++nt){
                    int colg = wn*128 + nt*8 + 2*qc;
                    float2 p0 = *(const float2*)(PjG + (size_t)row*D + colg);
                    float2 p8 = *(const float2*)(PjG + (size_t)(row+8)*D + colg);
                    float w0 = sm[MW64+colg], w1 = sm[MW64+colg+1];
                    float pi0 = sm[MPI+colg], pi1 = sm[MPI+colg+1];
                    float v0 = silu_f(cc[mt][nt][0] + sq0*w0 + pi0 + p0.x);
                    float v1 = silu_f(cc[mt][nt][1] + sq0*w1 + pi1 + p0.y);
                    float v2 = silu_f(cc[mt][nt][2] + sq8*w0 + pi0 + p8.x);
                    float v3 = silu_f(cc[mt][nt][3] + sq8*w1 + pi1 + p8.y);
                    *(half2*)&E1H[row*264 + colg]     = __floats2half2_rn(v0, v1);
                    *(half2*)&E1H[(row+8)*264 + colg] = __floats2half2_rn(v2, v3);
                }
            }
        }
        __syncthreads();   // E1 complete; W1 reads done (WS free)

        // ---- stage FULL W2 [256][264] halves (33792 floats = 8448 float4) ----
        {
            const float4* s4 = (const float4*)g_W2h[ch];
            float4* d4 = (float4*)(sm + WSO);
            #pragma unroll
            for (int it=0; it<33; ++it) d4[tid + it*256] = s4[tid + it*256];
        }
        __syncthreads();

        // ---- chain-2 mma: [128 x 256] @ [256 x 256], straight-line ----
        #pragma unroll
        for (int mt=0;mt<2;++mt)
            #pragma unroll
            for (int nt=0;nt<16;++nt)
                #pragma unroll
                for (int q=0;q<4;++q) cc[mt][nt][q]=0.f;

        #pragma unroll 2
        for (int kt = 0; kt < 16; ++kt){
            int kg = kt*16;
            uint32_t a[2][4];
            #pragma unroll
            for (int mt=0;mt<2;++mt){
                int rb = wm*32 + mt*16 + qr;
                a[mt][0] = *(const uint32_t*)&E1H[rb*264     + kg + 2*qc];
                a[mt][1] = *(const uint32_t*)&E1H[(rb+8)*264 + kg + 2*qc];
                a[mt][2] = *(const uint32_t*)&E1H[rb*264     + kg + 2*qc + 8];
                a[mt][3] = *(const uint32_t*)&E1H[(rb+8)*264 + kg + 2*qc + 8];
            }
            #pragma unroll
            for (int nt=0;nt<16;++nt){
                int nl = wn*128 + nt*8 + qr;
                uint32_t b0 = *(const uint32_t*)&WSH[nl*264 + kg + 2*qc];
                uint32_t b1 = *(const uint32_t*)&WSH[nl*264 + kg + 2*qc + 8];
                mma16(cc[0][nt], a[0][0],a[0][1],a[0][2],a[0][3], b0, b1);
                mma16(cc[1][nt], a[1][0],a[1][1],a[1][2],a[1][3], b0, b1);
            }
        }
        __syncthreads();   // all E1 reads done; E1 region free for m stash

        // ---- epilogue 2: rowsum + (ch0) half m-stash ----
        #pragma unroll
        for (int mt=0;mt<2;++mt){
            int row = wm*32 + mt*16 + qr;
            float pr0 = 0.f, pr8 = 0.f;
            #pragma unroll
            for (int nt=0;nt<16;++nt){
                int colg = wn*128 + nt*8 + 2*qc;
                float b0 = sm[MB2+colg], b1c = sm[MB2+colg+1];
                float w0 = sm[MWV+colg], w1 = sm[MWV+colg+1];
                float s0 = silu_f(cc[mt][nt][0]+b0);
                float s1 = silu_f(cc[mt][nt][1]+b1c);
                float s2 = silu_f(cc[mt][nt][2]+b0);
                float s3 = silu_f(cc[mt][nt][3]+b1c);
                pr0 += s0*w0 + s1*w1;
                pr8 += s2*w0 + s3*w1;
                if (ch == 0){
                    *(half2*)&E1H[row*264 + colg]     = __floats2half2_rn(s0, s1);
                    *(half2*)&E1H[(row+8)*264 + colg] = __floats2half2_rn(s2, s3);
                }
            }
            pr0 += __shfl_xor_sync(0xffffffffu, pr0, 1);
            pr0 += __shfl_xor_sync(0xffffffffu, pr0, 2);
            pr8 += __shfl_xor_sync(0xffffffffu, pr8, 1);
            pr8 += __shfl_xor_sync(0xffffffffu, pr8, 2);
            if (qc == 0){
                atomicAdd(&sm[MRS + row],     pr0);
                atomicAdd(&sm[MRS + row + 8], pr8);
            }
        }
        __syncthreads();

        if (tid < NPN){
            if (ch == 0)
                sm[MWG+tid] = sigm_f(sm[MRS+tid] + battv) * sm[MAD+tid];
            else
                sm[MWG+tid] = (sm[MRS+tid] + bx3v) * sm[MRN+tid] * sm[MAD+tid];
        }
        __syncthreads();

        if (ch == 0){
            float s = 0.f;
            #pragma unroll 8
            for (int j = 0; j < NPN; ++j)
                s += __half2float(E1H[j*264 + tid]) * sm[MWG+j];
            g_msg[gi*D + tid] = s;
        } else {
            if (warp < 4){
                int j = warp*32 + lane;
                float w = sm[MWG+j];
                float a0 = sm[MDX+j]*w, a1 = sm[MDY+j]*w, a2 = sm[MDZ+j]*w;
                #pragma unroll
                for (int off=16; off>=1; off>>=1){
                    a0 += __shfl_down_sync(0xffffffffu, a0, off);
                    a1 += __shfl_down_sync(0xffffffffu, a1, off);
                    a2 += __shfl_down_sync(0xffffffffu, a2, off);
                }
                if (lane == 0){
                    atomicAdd(&sm[MCR+0], a0);
                    atomicAdd(&sm[MCR+1], a1);
                    atomicAdd(&sm[MCR+2], a2);
                }
            }
        }
        __syncthreads();
    }

    if (tid < 3){
        float upd = sm[MCR+tid] / sm[MNN];
        outc[gi*3 + tid] = (coords[gi*3 + tid] + upd) * amask[gi];
    }
}

// =====================================================================
// node MLP: 4 nodes/CTA, grid 256, dynamic smem
// =====================================================================
__global__ void __launch_bounds__(256)
node_kernel(const float* __restrict__ inv, const float* __restrict__ amask,
            const float* __restrict__ Wh1, const float* __restrict__ bh1,
            const float* __restrict__ Wh2, const float* __restrict__ bh2,
            float* __restrict__ outf)
{
    extern __shared__ float nsm[];
    float* cat = nsm + ND_CAT;    // [4][512]
    float* ws  = nsm + ND_WS;     // [32][256]
    float* h1  = nsm + ND_H1;     // [4][256]
    const int g0 = blockIdx.x*4, c = threadIdx.x, tid = threadIdx.x;
    #pragma unroll
    for (int r=0;r<4;++r){
        cat[r*512 + c]       = inv[(size_t)(g0+r)*D + c];
        cat[r*512 + 256 + c] = g_msg[(size_t)(g0+r)*D + c];
    }

    float acc[4];
    float b1 = bh1[c];
    #pragma unroll
    for (int r=0;r<4;++r) acc[r]=b1;
    #pragma unroll 1
    for (int kc=0; kc<16; ++kc){
        __syncthreads();
        {
            int row = tid>>6, c4 = tid&63;
            #pragma unroll
            for (int it=0; it<8; ++it)
                ((float4*)ws)[(row+it*4)*64 + c4] =
                    ((const float4*)(Wh1 + (size_t)(kc*32 + row + it*4)*D))[c4];
        }
        __syncthreads();
        #pragma unroll 8
        for (int k=0;k<32;++k){
            float w = ws[k*256+c];
            int kk = kc*32+k;
            #pragma unroll
            for (int r=0;r<4;++r) acc[r] += cat[r*512+kk]*w;
        }
    }
    #pragma unroll
    for (int r=0;r<4;++r) h1[r*256+c] = silu_f(acc[r]);
    __syncthreads();

    float b2 = bh2[c];
    #pragma unroll
    for (int r=0;r<4;++r) acc[r]=b2;
    #pragma unroll 1
    for (int kc=0; kc<8; ++kc){
        __syncthreads();
        {
            int row = tid>>6, c4 = tid&63;
            #pragma unroll
            for (int it=0; it<8; ++it)
                ((float4*)ws)[(row+it*4)*64 + c4] =
                    ((const float4*)(Wh2 + (size_t)(kc*32 + row + it*4)*D))[c4];
        }
        __syncthreads();
        #pragma unroll 8
        for (int k=0;k<32;++k){
            float w = ws[k*256+c];
            int kk = kc*32+k;
            #pragma unroll
            for (int r=0;r<4;++r) acc[r] += h1[r*256+kk]*w;
        }
    }
    #pragma unroll
    for (int r=0;r<4;++r) outf[(size_t)(g0+r)*D + c] = acc[r]*amask[g0+r];
}

// =====================================================================
extern "C" void kernel_launch(void* const* d_in, const int* in_sizes, int n_in,
                              void* d_out, int out_size)
{
    const float* coords = (const float*)d_in[0];
    const float* inv    = (const float*)d_in[1];
    const float* adj    = (const float*)d_in[2];
    const float* amask  = (const float*)d_in[3];
    const float* ef     = (const float*)d_in[4];
    const float* We1    = (const float*)d_in[5];
    const float* be1    = (const float*)d_in[6];
    const float* We2    = (const float*)d_in[7];
    const float* be2    = (const float*)d_in[8];
    const float* Watt   = (const float*)d_in[9];
    const float* batt   = (const float*)d_in[10];
    const float* Wh1    = (const float*)d_in[11];
    const float* bh1    = (const float*)d_in[12];
    const float* Wh2    = (const float*)d_in[13];
    const float* bh2    = (const float*)d_in[14];
    const float* Wx1    = (const float*)d_in[15];
    const float* bx1    = (const float*)d_in[16];
    const float* Wx2    = (const float*)d_in[17];
    const float* bx2    = (const float*)d_in[18];
    const float* Wx3    = (const float*)d_in[19];
    const float* bx3    = (const float*)d_in[20];

    float* out  = (float*)d_out;
    float* outc = out;            // [8,128,3]
    float* outf = out + GN*3;     // [8,128,256]

    cudaFuncSetAttribute(edge_kernel, cudaFuncAttributeMaxDynamicSharedMemorySize, SMEM_BYTES);
    cudaFuncSetAttribute(node_kernel, cudaFuncAttributeMaxDynamicSharedMemorySize, ND_BYTES);

    prep_kernel<<<512, 256>>>(We1, Wx1, We2, Wx2);
    proj_kernel<<<GN/4, 256>>>(inv, We1, be1, Wx1, bx1);
    edge_kernel<<<GN, 256, SMEM_BYTES>>>(coords, adj, amask, ef,
                                         be2, Watt, batt, bx2, Wx3, bx3, outc);
    node_kernel<<<GN/4, 256, ND_BYTES>>>(inv, amask, Wh1, bh1, Wh2, bh2, outf);
}